// round 4
// baseline (speedup 1.0000x reference)
#include <cuda_runtime.h>

#define BB 4
#define SS 2048
#define DD 1024
#define HH 16
#define AA 64

// Scratch for projected heads: [B,H,S,A] each = 32 MB
__device__ float g_qh[BB*HH*SS*AA];
__device__ float g_kh[BB*HH*SS*AA];
__device__ float g_vh[BB*HH*SS*AA];

// ---------------------------------------------------------------------------
// Projection: out[b,h,s,a] = sum_d x[b,s,d] * W[h,d,a] + bias[h,a]
// grid (S/256, H, B), block 256 (tx=8 a-groups, ty=32 row-groups), 8x8 acc
// ---------------------------------------------------------------------------
__global__ __launch_bounds__(256) void proj_kernel(
    const float* __restrict__ x, const float* __restrict__ W,
    const float* __restrict__ bias, float* __restrict__ out)
{
    __shared__ float Xs[16][260];   // [k][row] (transposed), 256-row tile
    __shared__ float Ws[16][68];    // [k][a]

    const int s0 = blockIdx.x * 256;
    const int h  = blockIdx.y;
    const int b  = blockIdx.z;
    const int tid = threadIdx.x;
    const int tx = tid & 7;         // 8 groups of 8 a-columns
    const int ty = tid >> 3;        // 32 groups of 8 rows

    const float* xb = x + ((size_t)b * SS + s0) * DD;
    const float* Wh = W + (size_t)h * DD * AA;

    const int xr = tid >> 2;        // 0..63
    const int xk = (tid & 3) * 4;   // 0,4,8,12
    const int wk = tid >> 4;        // 0..15
    const int wa = (tid & 15) * 4;  // 0..60

    float acc[8][8];
    #pragma unroll
    for (int i = 0; i < 8; i++)
        #pragma unroll
        for (int j = 0; j < 8; j++) acc[i][j] = 0.0f;

    for (int k0 = 0; k0 < DD; k0 += 16) {
        __syncthreads();  // protect Xs/Ws from previous-iteration readers
        #pragma unroll
        for (int p = 0; p < 4; p++) {
            int row = p * 64 + xr;
            float4 v = *(const float4*)(xb + (size_t)row * DD + k0 + xk);
            Xs[xk + 0][row] = v.x;
            Xs[xk + 1][row] = v.y;
            Xs[xk + 2][row] = v.z;
            Xs[xk + 3][row] = v.w;
        }
        *(float4*)&Ws[wk][wa] = *(const float4*)(Wh + (size_t)(k0 + wk) * AA + wa);
        __syncthreads();

        #pragma unroll
        for (int kk = 0; kk < 16; kk++) {
            float4 a0 = *(const float4*)&Xs[kk][ty * 8];
            float4 a1 = *(const float4*)&Xs[kk][ty * 8 + 4];
            float4 w0 = *(const float4*)&Ws[kk][tx * 8];
            float4 w1 = *(const float4*)&Ws[kk][tx * 8 + 4];
            float av[8] = {a0.x, a0.y, a0.z, a0.w, a1.x, a1.y, a1.z, a1.w};
            float wv[8] = {w0.x, w0.y, w0.z, w0.w, w1.x, w1.y, w1.z, w1.w};
            #pragma unroll
            for (int i = 0; i < 8; i++)
                #pragma unroll
                for (int j = 0; j < 8; j++)
                    acc[i][j] = fmaf(av[i], wv[j], acc[i][j]);
        }
    }

    float4 b0 = *(const float4*)(bias + h * AA + tx * 8);
    float4 b1 = *(const float4*)(bias + h * AA + tx * 8 + 4);
    float* ob = out + (((size_t)b * HH + h) * SS + s0) * AA;
    #pragma unroll
    for (int i = 0; i < 8; i++) {
        int row = ty * 8 + i;
        float4 r0, r1;
        r0.x = acc[i][0] + b0.x; r0.y = acc[i][1] + b0.y;
        r0.z = acc[i][2] + b0.z; r0.w = acc[i][3] + b0.w;
        r1.x = acc[i][4] + b1.x; r1.y = acc[i][5] + b1.y;
        r1.z = acc[i][6] + b1.z; r1.w = acc[i][7] + b1.w;
        *(float4*)(ob + (size_t)row * AA + tx * 8)     = r0;
        *(float4*)(ob + (size_t)row * AA + tx * 8 + 4) = r1;
    }
}

// ---------------------------------------------------------------------------
// Flash attention (fp32, no scale/mask): 128-query x 128-key tiles,
// block 256 (tx = tid&15, ty = tid>>4), 8x8 S acc, 8x4 O acc.
// smem: Qs[64][132] Ks[64][132] Vs[128][68] Ps[128][132]  = 166 KB
// Ps uses a (ty&1)*4 float-XOR swizzle so PV float4 reads are conflict-free.
// ---------------------------------------------------------------------------
__global__ __launch_bounds__(256, 1) void attn_kernel(float* __restrict__ out)
{
    extern __shared__ float sm[];
    float (*Qs)[132] = (float(*)[132])(sm);                        // [a][row]
    float (*Ks)[132] = (float(*)[132])(sm + 64 * 132);             // [a][key]
    float (*Vs)[68]  = (float(*)[68]) (sm + 2 * 64 * 132);         // [key][a]
    float (*Ps)[132] = (float(*)[132])(sm + 2 * 64 * 132 + 128 * 68); // [row][key]

    const int s0 = blockIdx.x * 128;
    const int h  = blockIdx.y;
    const int b  = blockIdx.z;
    const int tid = threadIdx.x;
    const int tx = tid & 15;   // QK: 8 keys each (128); PV: 4 a-cols each (64)
    const int ty = tid >> 4;   // 8 rows each (128)

    const size_t base = ((size_t)b * HH + h) * SS * AA;
    const float* qh = g_qh + base;
    const float* kh = g_kh + base;
    const float* vh = g_vh + base;

    const int lrow = tid >> 1;          // 0..127
    const int ab   = (tid & 1) * 32;    // half of the 64 a-columns
    const int swz  = (ty & 1) * 4;      // Ps bank swizzle (constant per thread)

    // Load Q tile transposed: Qs[a][row]
    {
        const float* src = qh + (size_t)(s0 + lrow) * AA + ab;
        #pragma unroll
        for (int g = 0; g < 8; g++) {
            float4 v = *(const float4*)(src + g * 4);
            int a = ab + g * 4;
            Qs[a + 0][lrow] = v.x;
            Qs[a + 1][lrow] = v.y;
            Qs[a + 2][lrow] = v.z;
            Qs[a + 3][lrow] = v.w;
        }
    }

    float m[8], l[8], o[8][4];
    #pragma unroll
    for (int i = 0; i < 8; i++) {
        m[i] = -1e30f;
        l[i] = 0.0f;
        #pragma unroll
        for (int j = 0; j < 4; j++) o[i][j] = 0.0f;
    }

    for (int kt = 0; kt < SS; kt += 128) {
        __syncthreads();  // all warps done with previous Ks/Vs/Ps (and Qs init)
        {
            const float* ks = kh + (size_t)(kt + lrow) * AA + ab;
            const float* vs = vh + (size_t)(kt + lrow) * AA + ab;
            #pragma unroll
            for (int g = 0; g < 8; g++) {
                float4 kv = *(const float4*)(ks + g * 4);
                int a = ab + g * 4;
                Ks[a + 0][lrow] = kv.x;
                Ks[a + 1][lrow] = kv.y;
                Ks[a + 2][lrow] = kv.z;
                Ks[a + 3][lrow] = kv.w;
                *(float4*)&Vs[lrow][a] = *(const float4*)(vs + g * 4);
            }
        }
        __syncthreads();

        // ---- S = Q K^T (dot over a), 8x8 per thread ----
        float sacc[8][8];
        #pragma unroll
        for (int i = 0; i < 8; i++)
            #pragma unroll
            for (int j = 0; j < 8; j++) sacc[i][j] = 0.0f;

        #pragma unroll 4
        for (int kk = 0; kk < 64; kk++) {
            float4 q0 = *(const float4*)&Qs[kk][ty * 8];
            float4 q1 = *(const float4*)&Qs[kk][ty * 8 + 4];
            float4 k0 = *(const float4*)&Ks[kk][tx * 8];
            float4 k1 = *(const float4*)&Ks[kk][tx * 8 + 4];
            float qv[8] = {q0.x, q0.y, q0.z, q0.w, q1.x, q1.y, q1.z, q1.w};
            float kv[8] = {k0.x, k0.y, k0.z, k0.w, k1.x, k1.y, k1.z, k1.w};
            #pragma unroll
            for (int i = 0; i < 8; i++)
                #pragma unroll
                for (int j = 0; j < 8; j++)
                    sacc[i][j] = fmaf(qv[i], kv[j], sacc[i][j]);
        }

        // ---- online softmax (row stats across the 16 tx lanes) ----
        #pragma unroll
        for (int i = 0; i < 8; i++) {
            float rm = sacc[i][0];
            #pragma unroll
            for (int j = 1; j < 8; j++) rm = fmaxf(rm, sacc[i][j]);
            rm = fmaxf(rm, __shfl_xor_sync(0xffffffffu, rm, 1, 16));
            rm = fmaxf(rm, __shfl_xor_sync(0xffffffffu, rm, 2, 16));
            rm = fmaxf(rm, __shfl_xor_sync(0xffffffffu, rm, 4, 16));
            rm = fmaxf(rm, __shfl_xor_sync(0xffffffffu, rm, 8, 16));
            float mn = fmaxf(m[i], rm);
            float sc = __expf(m[i] - mn);
            m[i] = mn;
            float rs = 0.0f;
            #pragma unroll
            for (int j = 0; j < 8; j++) {
                sacc[i][j] = __expf(sacc[i][j] - mn);
                rs += sacc[i][j];
            }
            rs += __shfl_xor_sync(0xffffffffu, rs, 1, 16);
            rs += __shfl_xor_sync(0xffffffffu, rs, 2, 16);
            rs += __shfl_xor_sync(0xffffffffu, rs, 4, 16);
            rs += __shfl_xor_sync(0xffffffffu, rs, 8, 16);
            l[i] = l[i] * sc + rs;
            #pragma unroll
            for (int j = 0; j < 4; j++) o[i][j] *= sc;

            // store P row (swizzled): logical cols tx*8..tx*8+7
            int row = ty * 8 + i;
            float4 p0, p1;
            p0.x = sacc[i][0]; p0.y = sacc[i][1]; p0.z = sacc[i][2]; p0.w = sacc[i][3];
            p1.x = sacc[i][4]; p1.y = sacc[i][5]; p1.z = sacc[i][6]; p1.w = sacc[i][7];
            *(float4*)&Ps[row][(tx * 8)     ^ swz] = p0;
            *(float4*)&Ps[row][(tx * 8 + 4) ^ swz] = p1;
        }
        __syncthreads();

        // ---- O += P V (dot over 128 keys), 8 rows x 4 a-cols per thread ----
        #pragma unroll 2
        for (int kk0 = 0; kk0 < 128; kk0 += 4) {
            float4 p[8];
            #pragma unroll
            for (int i = 0; i < 8; i++)
                p[i] = *(const float4*)&Ps[ty * 8 + i][kk0 ^ swz];
            float4 v0 = *(const float4*)&Vs[kk0 + 0][tx * 4];
            float4 v1 = *(const float4*)&Vs[kk0 + 1][tx * 4];
            float4 v2 = *(const float4*)&Vs[kk0 + 2][tx * 4];
            float4 v3 = *(const float4*)&Vs[kk0 + 3][tx * 4];
            #pragma unroll
            for (int i = 0; i < 8; i++) {
                o[i][0] = fmaf(p[i].x, v0.x, o[i][0]);
                o[i][1] = fmaf(p[i].x, v0.y, o[i][1]);
                o[i][2] = fmaf(p[i].x, v0.z, o[i][2]);
                o[i][3] = fmaf(p[i].x, v0.w, o[i][3]);
                o[i][0] = fmaf(p[i].y, v1.x, o[i][0]);
                o[i][1] = fmaf(p[i].y, v1.y, o[i][1]);
                o[i][2] = fmaf(p[i].y, v1.z, o[i][2]);
                o[i][3] = fmaf(p[i].y, v1.w, o[i][3]);
                o[i][0] = fmaf(p[i].z, v2.x, o[i][0]);
                o[i][1] = fmaf(p[i].z, v2.y, o[i][1]);
                o[i][2] = fmaf(p[i].z, v2.z, o[i][2]);
                o[i][3] = fmaf(p[i].z, v2.w, o[i][3]);
                o[i][0] = fmaf(p[i].w, v3.x, o[i][0]);
                o[i][1] = fmaf(p[i].w, v3.y, o[i][1]);
                o[i][2] = fmaf(p[i].w, v3.z, o[i][2]);
                o[i][3] = fmaf(p[i].w, v3.w, o[i][3]);
            }
        }
    }

    // normalize + write out[b, s, h*A + a]
    #pragma unroll
    for (int i = 0; i < 8; i++) {
        float inv = 1.0f / l[i];
        float4 r;
        r.x = o[i][0] * inv;
        r.y = o[i][1] * inv;
        r.z = o[i][2] * inv;
        r.w = o[i][3] * inv;
        *(float4*)(out + ((size_t)b * SS + s0 + ty * 8 + i) * (HH * AA)
                       + h * AA + tx * 4) = r;
    }
}

// ---------------------------------------------------------------------------
extern "C" void kernel_launch(void* const* d_in, const int* in_sizes, int n_in,
                              void* d_out, int out_size)
{
    const float* q  = (const float*)d_in[0];
    const float* k  = (const float*)d_in[1];
    const float* v  = (const float*)d_in[2];
    const float* Wq = (const float*)d_in[3];
    const float* bq = (const float*)d_in[4];
    const float* Wk = (const float*)d_in[5];
    const float* bk = (const float*)d_in[6];
    const float* Wv = (const float*)d_in[7];
    const float* bv = (const float*)d_in[8];
    float* out = (float*)d_out;

    float *qh, *kh, *vh;
    cudaGetSymbolAddress((void**)&qh, g_qh);
    cudaGetSymbolAddress((void**)&kh, g_kh);
    cudaGetSymbolAddress((void**)&vh, g_vh);

    dim3 pgrid(SS / 256, HH, BB);
    proj_kernel<<<pgrid, 256>>>(q, Wq, bq, qh);
    proj_kernel<<<pgrid, 256>>>(k, Wk, bk, kh);
    proj_kernel<<<pgrid, 256>>>(v, Wv, bv, vh);

    const int smem_bytes = (2 * 64 * 132 + 128 * 68 + 128 * 132) * (int)sizeof(float); // 169984
    cudaFuncSetAttribute(attn_kernel,
                         cudaFuncAttributeMaxDynamicSharedMemorySize, smem_bytes);
    dim3 agrid(SS / 128, HH, BB);
    attn_kernel<<<agrid, 256, smem_bytes>>>(out);
}

// round 10
// speedup vs baseline: 2.7345x; 2.7345x over previous
#include <cuda_runtime.h>
#include <cuda_bf16.h>
#include <cstdint>

#define BB 4
#define SS 2048
#define DD 1024
#define HH 16
#define AA 64
typedef __nv_bfloat16 bf16;
typedef unsigned int u32;

__device__ bf16 g_xh[3][BB*SS*DD], g_xl[3][BB*SS*DD];
__device__ bf16 g_wh[3][HH*AA*DD], g_wl[3][HH*AA*DD];
__device__ bf16 g_ph[3][BB*HH*SS*AA], g_pl[3][BB*HH*SS*AA];
__device__ bf16 g_vth[BB*HH*AA*SS], g_vtl[BB*HH*AA*SS];

__device__ __forceinline__ void mma16816(float* c, const u32* a, const u32* b){
  asm volatile("mma.sync.aligned.m16n8k16.row.col.f32.bf16.bf16.f32 "
    "{%0,%1,%2,%3},{%4,%5,%6,%7},{%8,%9},{%0,%1,%2,%3};"
    : "+f"(c[0]),"+f"(c[1]),"+f"(c[2]),"+f"(c[3])
    : "r"(a[0]),"r"(a[1]),"r"(a[2]),"r"(a[3]),"r"(b[0]),"r"(b[1]));
}
__device__ __forceinline__ u32 packbf(float x, float y){
  __nv_bfloat162 h=__halves2bfloat162(__float2bfloat16(x),__float2bfloat16(y));
  return *(u32*)&h;
}
__device__ __forceinline__ u32 packlo(float x, float y, u32 hi){
  __nv_bfloat162 h=*(__nv_bfloat162*)&hi;
  return packbf(x-__bfloat162float(h.x), y-__bfloat162float(h.y));
}

// ---- fp32 -> bf16 hi/lo split ----
__global__ __launch_bounds__(256) void splitk(const float* __restrict__ x, bf16* __restrict__ hi, bf16* __restrict__ lo){
  size_t i=((size_t)blockIdx.x*256+threadIdx.x)*4;
  float4 v=*(const float4*)(x+i);
  u32 h0=packbf(v.x,v.y), h1=packbf(v.z,v.w);
  *(u32*)(hi+i)=h0; *(u32*)(hi+i+2)=h1;
  *(u32*)(lo+i)=packlo(v.x,v.y,h0); *(u32*)(lo+i+2)=packlo(v.z,v.w,h1);
}

// ---- W[H,D,A] -> WT hi/lo [H,A,D] ----
__global__ __launch_bounds__(256) void wsplitk(const float* __restrict__ W, bf16* __restrict__ wh, bf16* __restrict__ wl){
  __shared__ float sw[64][68];
  const int h=blockIdx.y, d0=blockIdx.x*64, t=threadIdx.x;
  { int r=t>>2, c=(t&3)*16;
    const float* src=W+((size_t)h*DD+d0+r)*AA+c;
    #pragma unroll
    for(int j=0;j<4;j++){float4 v=*(const float4*)(src+j*4);
      sw[r][c+j*4]=v.x;sw[r][c+j*4+1]=v.y;sw[r][c+j*4+2]=v.z;sw[r][c+j*4+3]=v.w;} }
  __syncthreads();
  int a=t>>2, dc=(t&3)*16;
  u32 ph[8],pl[8];
  #pragma unroll
  for(int j=0;j<8;j++){
    float f0=sw[dc+2*j][a],f1=sw[dc+2*j+1][a];
    ph[j]=packbf(f0,f1); pl[j]=packlo(f0,f1,ph[j]);
  }
  bf16* dh=wh+((size_t)h*AA+a)*DD+d0+dc;
  bf16* dl=wl+((size_t)h*AA+a)*DD+d0+dc;
  *(uint4*)dh=make_uint4(ph[0],ph[1],ph[2],ph[3]); *(uint4*)(dh+8)=make_uint4(ph[4],ph[5],ph[6],ph[7]);
  *(uint4*)dl=make_uint4(pl[0],pl[1],pl[2],pl[3]); *(uint4*)(dl+8)=make_uint4(pl[4],pl[5],pl[6],pl[7]);
}

// ---- V heads [b,h,s,a] -> [b,h,a,s] ----
__global__ __launch_bounds__(256) void vtk(const bf16* __restrict__ vh,const bf16* __restrict__ vl,
    bf16* __restrict__ th,bf16* __restrict__ tl){
  __shared__ bf16 buf[128][72];
  const int s0=blockIdx.x*128,t=threadIdx.x;
  const size_t bh=(size_t)blockIdx.z*HH+blockIdx.y;
  for(int part=0;part<2;part++){
    const bf16* src=(part?vl:vh)+(bh*SS+s0)*AA;
    bf16* dst=(part?tl:th)+bh*(size_t)AA*SS;
    __syncthreads();
    for(int j=t;j<1024;j+=256){int s=j>>3,ac=(j&7)*8;
      *(uint4*)&buf[s][ac]=*(const uint4*)(src+(size_t)s*AA+ac);}
    __syncthreads();
    int a=t>>2,sg=(t&3)*32;
    u32 pk[16];
    #pragma unroll
    for(int j=0;j<16;j++)
      {__nv_bfloat162 p=__halves2bfloat162(buf[sg+2*j][a],buf[sg+2*j+1][a]);pk[j]=*(u32*)&p;}
    bf16* d=dst+(size_t)a*SS+s0+sg;
    #pragma unroll
    for(int j=0;j<4;j++)*(uint4*)(d+j*8)=make_uint4(pk[4*j],pk[4*j+1],pk[4*j+2],pk[4*j+3]);
  }
}

// ---- Projection GEMM via mma.sync: 128 rows x 64 cols (1 head), K=1024 ----
__global__ __launch_bounds__(256,2) void projk(const bf16* __restrict__ xh,const bf16* __restrict__ xl,
    const bf16* __restrict__ wh,const bf16* __restrict__ wl,const float* __restrict__ bias,
    bf16* __restrict__ oh,bf16* __restrict__ ol){
  extern __shared__ bf16 smb[];
  bf16 *Xh=smb, *Xl=Xh+128*72, *Wh=Xl+128*72, *Wl=Wh+64*72;  // 27648 elems
  const int t=threadIdx.x, w=t>>5, lane=t&31;
  const int s0=blockIdx.x*128, h=blockIdx.y, b=blockIdx.z;
  const int gid=lane>>2, tig=lane&3;
  const int r0=16*w+gid;
  const bf16* xhp=xh+((size_t)b*SS+s0)*DD;
  const bf16* xlp=xl+((size_t)b*SS+s0)*DD;
  const bf16* whp=wh+(size_t)h*AA*DD;
  const bf16* wlp=wl+(size_t)h*AA*DD;
  float c[8][4];
  #pragma unroll
  for(int j=0;j<8;j++){c[j][0]=0;c[j][1]=0;c[j][2]=0;c[j][3]=0;}
  for(int cc=0;cc<16;cc++){
    int d0=cc*64;
    __syncthreads();
    #pragma unroll
    for(int j=0;j<4;j++){int g=t+256*j,r=g>>3,v=(g&7)*8;
      *(uint4*)&Xh[r*72+v]=*(const uint4*)(xhp+(size_t)r*DD+d0+v);
      *(uint4*)&Xl[r*72+v]=*(const uint4*)(xlp+(size_t)r*DD+d0+v);}
    #pragma unroll
    for(int j=0;j<2;j++){int g=t+256*j,a=g>>3,v=(g&7)*8;
      *(uint4*)&Wh[a*72+v]=*(const uint4*)(whp+(size_t)a*DD+d0+v);
      *(uint4*)&Wl[a*72+v]=*(const uint4*)(wlp+(size_t)a*DD+d0+v);}
    __syncthreads();
    #pragma unroll
    for(int ks=0;ks<4;ks++){
      int k0=16*ks;
      u32 ah[4],al[4];
      ah[0]=*(u32*)&Xh[ r0   *72+k0+2*tig]; ah[1]=*(u32*)&Xh[(r0+8)*72+k0+2*tig];
      ah[2]=*(u32*)&Xh[ r0   *72+k0+8+2*tig]; ah[3]=*(u32*)&Xh[(r0+8)*72+k0+8+2*tig];
      al[0]=*(u32*)&Xl[ r0   *72+k0+2*tig]; al[1]=*(u32*)&Xl[(r0+8)*72+k0+2*tig];
      al[2]=*(u32*)&Xl[ r0   *72+k0+8+2*tig]; al[3]=*(u32*)&Xl[(r0+8)*72+k0+8+2*tig];
      #pragma unroll
      for(int j=0;j<8;j++){
        int n=8*j+gid;
        u32 bh[2],bl[2];
        bh[0]=*(u32*)&Wh[n*72+k0+2*tig]; bh[1]=*(u32*)&Wh[n*72+k0+8+2*tig];
        bl[0]=*(u32*)&Wl[n*72+k0+2*tig]; bl[1]=*(u32*)&Wl[n*72+k0+8+2*tig];
        mma16816(c[j],ah,bh);
        mma16816(c[j],ah,bl);
        mma16816(c[j],al,bh);
      }
    }
  }
  // epilogue: + bias, split, store hi/lo
  bf16* oph=oh+(((size_t)b*HH+h)*SS+s0)*AA;
  bf16* opl=ol+(((size_t)b*HH+h)*SS+s0)*AA;
  #pragma unroll
  for(int j=0;j<8;j++){
    int n=8*j+2*tig;
    float bs0=bias[h*AA+n], bs1=bias[h*AA+n+1];
    float f0=c[j][0]+bs0, f1=c[j][1]+bs1, f2=c[j][2]+bs0, f3=c[j][3]+bs1;
    u32 h0=packbf(f0,f1), h1=packbf(f2,f3);
    *(u32*)(oph+(size_t)r0*AA+n)    =h0; *(u32*)(opl+(size_t)r0*AA+n)    =packlo(f0,f1,h0);
    *(u32*)(oph+(size_t)(r0+8)*AA+n)=h1; *(u32*)(opl+(size_t)(r0+8)*AA+n)=packlo(f2,f3,h1);
  }
}

// ---- Flash attention via mma.sync: 128 q x 64-key tiles, shifted softmax ----
__global__ __launch_bounds__(256,2) void attnk(const bf16* __restrict__ qh_,const bf16* __restrict__ ql_,
    const bf16* __restrict__ kh_,const bf16* __restrict__ kl_,
    const bf16* __restrict__ vh_,const bf16* __restrict__ vl_,float* __restrict__ out){
  extern __shared__ bf16 smb[];
  bf16 *Qh=smb, *Ql=Qh+128*72, *Kh=Ql+128*72, *Kl=Kh+64*72, *Vh=Kl+64*72, *Vl=Vh+64*72; // 36864 elems
  const int t=threadIdx.x, w=t>>5, lane=t&31;
  const int s0=blockIdx.x*128, h=blockIdx.y, b=blockIdx.z;
  const int gid=lane>>2, tig=lane&3;
  const int r0=16*w+gid;
  const size_t hb=((size_t)b*HH+h)*SS*AA;
  const size_t vb=((size_t)b*HH+h)*(size_t)AA*SS;
  #pragma unroll
  for(int j=0;j<4;j++){int g=t+256*j,r=g>>3,v=(g&7)*8;
    *(uint4*)&Qh[r*72+v]=*(const uint4*)(qh_+hb+(size_t)(s0+r)*AA+v);
    *(uint4*)&Ql[r*72+v]=*(const uint4*)(ql_+hb+(size_t)(s0+r)*AA+v);}
  float o[8][4];
  #pragma unroll
  for(int j=0;j<8;j++){o[j][0]=0;o[j][1]=0;o[j][2]=0;o[j][3]=0;}
  float ls0=0.f, ls1=0.f;
  for(int kt=0;kt<32;kt++){
    __syncthreads();
    #pragma unroll
    for(int j=0;j<2;j++){int g=t+256*j,r=g>>3,v=(g&7)*8;
      *(uint4*)&Kh[r*72+v]=*(const uint4*)(kh_+hb+(size_t)(kt*64+r)*AA+v);
      *(uint4*)&Kl[r*72+v]=*(const uint4*)(kl_+hb+(size_t)(kt*64+r)*AA+v);
      *(uint4*)&Vh[r*72+v]=*(const uint4*)(vh_+vb+(size_t)r*SS+kt*64+v);
      *(uint4*)&Vl[r*72+v]=*(const uint4*)(vl_+vb+(size_t)r*SS+kt*64+v);}
    __syncthreads();
    // S = Q K^T
    float c[8][4];
    #pragma unroll
    for(int j=0;j<8;j++){c[j][0]=0;c[j][1]=0;c[j][2]=0;c[j][3]=0;}
    #pragma unroll
    for(int ks=0;ks<4;ks++){
      int k0=16*ks;
      u32 ah[4],al[4];
      ah[0]=*(u32*)&Qh[ r0   *72+k0+2*tig]; ah[1]=*(u32*)&Qh[(r0+8)*72+k0+2*tig];
      ah[2]=*(u32*)&Qh[ r0   *72+k0+8+2*tig]; ah[3]=*(u32*)&Qh[(r0+8)*72+k0+8+2*tig];
      al[0]=*(u32*)&Ql[ r0   *72+k0+2*tig]; al[1]=*(u32*)&Ql[(r0+8)*72+k0+2*tig];
      al[2]=*(u32*)&Ql[ r0   *72+k0+8+2*tig]; al[3]=*(u32*)&Ql[(r0+8)*72+k0+8+2*tig];
      #pragma unroll
      for(int j=0;j<8;j++){
        int n=8*j+gid;
        u32 bh[2],bl[2];
        bh[0]=*(u32*)&Kh[n*72+k0+2*tig]; bh[1]=*(u32*)&Kh[n*72+k0+8+2*tig];
        bl[0]=*(u32*)&Kl[n*72+k0+2*tig]; bl[1]=*(u32*)&Kl[n*72+k0+8+2*tig];
        mma16816(c[j],ah,bh);
        mma16816(c[j],ah,bl);
        mma16816(c[j],al,bh);
      }
    }
    // P = exp(S-30); pack to bf16 hi/lo fragments (C-frag == A-frag layout)
    u32 ph2[8][2], pl2[8][2];
    #pragma unroll
    for(int j=0;j<8;j++){
      float e0=__expf(c[j][0]-30.f), e1=__expf(c[j][1]-30.f);
      float e2=__expf(c[j][2]-30.f), e3=__expf(c[j][3]-30.f);
      ls0+=e0+e1; ls1+=e2+e3;
      ph2[j][0]=packbf(e0,e1); pl2[j][0]=packlo(e0,e1,ph2[j][0]);
      ph2[j][1]=packbf(e2,e3); pl2[j][1]=packlo(e2,e3,ph2[j][1]);
    }
    // O += P V
    #pragma unroll
    for(int ks=0;ks<4;ks++){
      int k0=16*ks;
      u32 ah[4]={ph2[2*ks][0],ph2[2*ks][1],ph2[2*ks+1][0],ph2[2*ks+1][1]};
      u32 al[4]={pl2[2*ks][0],pl2[2*ks][1],pl2[2*ks+1][0],pl2[2*ks+1][1]};
      #pragma unroll
      for(int j=0;j<8;j++){
        int n=8*j+gid;
        u32 bh[2],bl[2];
        bh[0]=*(u32*)&Vh[n*72+k0+2*tig]; bh[1]=*(u32*)&Vh[n*72+k0+8+2*tig];
        bl[0]=*(u32*)&Vl[n*72+k0+2*tig]; bl[1]=*(u32*)&Vl[n*72+k0+8+2*tig];
        mma16816(o[j],ah,bh);
        mma16816(o[j],ah,bl);
        mma16816(o[j],al,bh);
      }
    }
  }
  ls0+=__shfl_xor_sync(0xffffffffu,ls0,1); ls0+=__shfl_xor_sync(0xffffffffu,ls0,2);
  ls1+=__shfl_xor_sync(0xffffffffu,ls1,1); ls1+=__shfl_xor_sync(0xffffffffu,ls1,2);
  float inv0=1.f/ls0, inv1=1.f/ls1;
  float* op0=out+((size_t)b*SS+s0+r0)*(HH*AA)+h*AA;
  float* op1=op0+(size_t)8*(HH*AA);
  #pragma unroll
  for(int j=0;j<8;j++){
    int n=8*j+2*tig;
    float2 v0={o[j][0]*inv0,o[j][1]*inv0};
    float2 v1={o[j][2]*inv1,o[j][3]*inv1};
    *(float2*)(op0+n)=v0;
    *(float2*)(op1+n)=v1;
  }
}

// ---------------------------------------------------------------------------
extern "C" void kernel_launch(void* const* d_in, const int* in_sizes, int n_in,
                              void* d_out, int out_size)
{
  bf16 *xh,*xl,*wh,*wl,*ph,*pl,*vth,*vtl;
  cudaGetSymbolAddress((void**)&xh,g_xh); cudaGetSymbolAddress((void**)&xl,g_xl);
  cudaGetSymbolAddress((void**)&wh,g_wh); cudaGetSymbolAddress((void**)&wl,g_wl);
  cudaGetSymbolAddress((void**)&ph,g_ph); cudaGetSymbolAddress((void**)&pl,g_pl);
  cudaGetSymbolAddress((void**)&vth,g_vth); cudaGetSymbolAddress((void**)&vtl,g_vtl);
  const size_t NX=(size_t)BB*SS*DD, NW=(size_t)HH*AA*DD, NP=(size_t)BB*HH*SS*AA;

  for(int i=0;i<3;i++){
    splitk<<<8192,256>>>((const float*)d_in[i], xh+i*NX, xl+i*NX);
    wsplitk<<<dim3(16,16),256>>>((const float*)d_in[3+2*i], wh+i*NW, wl+i*NW);
  }
  const int psm=27648*(int)sizeof(bf16);  // 55296
  cudaFuncSetAttribute(projk, cudaFuncAttributeMaxDynamicSharedMemorySize, psm);
  for(int i=0;i<3;i++)
    projk<<<dim3(16,16,4),256,psm>>>(xh+i*NX, xl+i*NX, wh+i*NW, wl+i*NW,
                                     (const float*)d_in[4+2*i], ph+i*NP, pl+i*NP);
  vtk<<<dim3(16,16,4),256>>>(ph+2*NP, pl+2*NP, vth, vtl);
  const int asm_=36864*(int)sizeof(bf16); // 73728
  cudaFuncSetAttribute(attnk, cudaFuncAttributeMaxDynamicSharedMemorySize, asm_);
  attnk<<<dim3(16,16,4),256,asm_>>>(ph, pl, ph+NP, pl+NP, vth, vtl, (float*)d_out);
}